// round 1
// baseline (speedup 1.0000x reference)
#include <cuda_runtime.h>
#include <cuda_bf16.h>
#include <math.h>
#include <stdint.h>

// ---------------- problem constants ----------------
#define VMAX 50000
#define EMAX 600000
#define Dg   256
#define Kp   20     // kron projection dim
#define OUTD 256

// ---------------- device scratch (static; no allocation allowed) ----------------
__device__ float g_npj[(size_t)VMAX * Kp];
__device__ float g_ad[VMAX];
__device__ float g_as[VMAX];
__device__ float g_hv[(size_t)VMAX * Dg];
__device__ float g_T[(size_t)VMAX * Kp * OUTD];      // 1.024 GB
__device__ int   g_deg[VMAX];
__device__ int   g_offs[VMAX + 1];
__device__ int   g_cursor[VMAX];
__device__ int   g_eids[EMAX];
__device__ float g_att[EMAX];
__device__ float g_ctx[(size_t)VMAX * Dg];
__device__ float g_kf[(size_t)VMAX * OUTD];
__device__ float g_gi[(size_t)VMAX * 3 * Dg];
__device__ float g_gh[(size_t)VMAX * 3 * Dg];
__device__ float g_cat[(size_t)VMAX * (Dg + OUTD)];

// ---------------- helpers ----------------
__device__ __forceinline__ float warp_sum(float v) {
    #pragma unroll
    for (int o = 16; o; o >>= 1) v += __shfl_xor_sync(0xffffffffu, v, o);
    return v;
}
__device__ __forceinline__ float warp_max(float v) {
    #pragma unroll
    for (int o = 16; o; o >>= 1) v = fmaxf(v, __shfl_xor_sync(0xffffffffu, v, o));
    return v;
}

// block (256 thr) LN stats over one value per thread
__device__ __forceinline__ void ln_stats_256(float v, float* mu, float* rs) {
    __shared__ float s1[8], s2[8];
    float a = v, b = v * v;
    a = warp_sum(a); b = warp_sum(b);
    int w = threadIdx.x >> 5, l = threadIdx.x & 31;
    if (l == 0) { s1[w] = a; s2[w] = b; }
    __syncthreads();
    if (w == 0) {
        a = (l < 8) ? s1[l] : 0.f;
        b = (l < 8) ? s2[l] : 0.f;
        #pragma unroll
        for (int o = 4; o; o >>= 1) { a += __shfl_xor_sync(0xffffffffu, a, o); b += __shfl_xor_sync(0xffffffffu, b, o); }
        if (l == 0) { s1[0] = a; s2[0] = b; }
    }
    __syncthreads();
    float m = s1[0] * (1.f / 256.f);
    float var = s2[0] * (1.f / 256.f) - m * m;
    *mu = m;
    *rs = rsqrtf(var + 1e-5f);
}

// ---------------- tiny utility kernels ----------------
__global__ void k_zero_int(int* p, int n) {
    for (int i = blockIdx.x * blockDim.x + threadIdx.x; i < n; i += gridDim.x * blockDim.x) p[i] = 0;
}
__global__ void k_hist(const int* __restrict__ dst, int* deg, int E) {
    for (int i = blockIdx.x * blockDim.x + threadIdx.x; i < E; i += gridDim.x * blockDim.x)
        atomicAdd(&deg[dst[i]], 1);
}
// exclusive scan over V in ONE block of 1024 threads
__global__ void k_scan(const int* __restrict__ deg, int* offs, int V) {
    __shared__ int sums[1024];
    int tid = threadIdx.x;
    int per = (V + 1023) / 1024;
    int start = tid * per;
    int s = 0;
    for (int i = 0; i < per; i++) { int idx = start + i; if (idx < V) s += deg[idx]; }
    sums[tid] = s;
    __syncthreads();
    for (int off = 1; off < 1024; off <<= 1) {
        int v = 0;
        if (tid >= off) v = sums[tid - off];
        __syncthreads();
        if (tid >= off) sums[tid] += v;
        __syncthreads();
    }
    int base = (tid > 0) ? sums[tid - 1] : 0;
    int run = base;
    for (int i = 0; i < per; i++) {
        int idx = start + i;
        if (idx < V) { offs[idx] = run; run += deg[idx]; }
    }
    if (tid == 1023) offs[V] = sums[1023];
}
__global__ void k_copy_int(const int* __restrict__ a, int* b, int n) {
    for (int i = blockIdx.x * blockDim.x + threadIdx.x; i < n; i += gridDim.x * blockDim.x) b[i] = a[i];
}
__global__ void k_scatter(const int* __restrict__ dst, int* cursor, int* eids, int E) {
    for (int i = blockIdx.x * blockDim.x + threadIdx.x; i < E; i += gridDim.x * blockDim.x) {
        int p = atomicAdd(&cursor[dst[i]], 1);
        eids[p] = i;
    }
}

// ---------------- npj = relu(LN(x@Wp+bp)) + attention node partials ----------------
__global__ void k_npj(const float* __restrict__ nf, const float* __restrict__ Wp,
                      const float* __restrict__ bp, const float* __restrict__ gp,
                      const float* __restrict__ betap, const float* __restrict__ We,
                      float* npj, float* ad, float* as_, int V) {
    int warp = (blockIdx.x * blockDim.x + threadIdx.x) >> 5;
    int lane = threadIdx.x & 31;
    if (warp >= V) return;
    const float* x = nf + (size_t)warp * Dg;
    float xr[8];
    #pragma unroll
    for (int j = 0; j < 8; j++) xr[j] = x[j * 32 + lane];
    // attention per-node dots (he = [dst feats | src feats])
    float pa = 0.f, pb = 0.f;
    #pragma unroll
    for (int j = 0; j < 8; j++) { int i = j * 32 + lane; pa += xr[j] * We[i]; pb += xr[j] * We[Dg + i]; }
    pa = warp_sum(pa); pb = warp_sum(pb);
    if (lane == 0) { ad[warp] = pa; as_[warp] = pb; }
    // project to K=20
    float val = 0.f;
    for (int k = 0; k < Kp; k++) {
        float p = 0.f;
        #pragma unroll
        for (int j = 0; j < 8; j++) { int i = j * 32 + lane; p += xr[j] * Wp[i * Kp + k]; }
        p = warp_sum(p);
        p += bp[k];
        if (lane == k) val = p;
    }
    // LN over 20 lanes
    float c = (lane < Kp) ? val : 0.f;
    float s = warp_sum(c);
    float s2 = warp_sum(c * c);
    float mu = s / (float)Kp;
    float var = s2 / (float)Kp - mu * mu;
    float rs = rsqrtf(var + 1e-5f);
    if (lane < Kp) {
        float y = (val - mu) * rs * gp[lane] + betap[lane];
        npj[(size_t)warp * Kp + lane] = fmaxf(y, 0.f);
    }
}

// ---------------- T[v,a,o] = sum_k npj[v,k] * Wk[(a*20+k), o] ----------------
__global__ void k_T(const float* __restrict__ npj, const float* __restrict__ Wk,
                    float* __restrict__ T, int V) {
    __shared__ float pn[16][Kp];
    int v0 = blockIdx.x * 16;
    int tid = threadIdx.x;  // 256
    for (int i = tid; i < 16 * Kp; i += 256) {
        int n = i / Kp, k = i % Kp;
        pn[n][k] = (v0 + n < V) ? npj[(size_t)(v0 + n) * Kp + k] : 0.f;
    }
    __syncthreads();
    int o = tid;
    #pragma unroll 1
    for (int a = 0; a < Kp; a++) {
        float w[Kp];
        #pragma unroll
        for (int k = 0; k < Kp; k++) w[k] = Wk[(size_t)(a * Kp + k) * OUTD + o];
        #pragma unroll 1
        for (int n = 0; n < 16; n++) {
            int v = v0 + n;
            if (v >= V) break;
            float t = 0.f;
            #pragma unroll
            for (int k = 0; k < Kp; k++) t += pn[n][k] * w[k];
            T[(size_t)v * (Kp * OUTD) + a * OUTD + o] = t;
        }
    }
}

// ---------------- kron branch: per-dst-node, T in shared, warp per edge ----------------
__global__ void k_kron(const int* __restrict__ src, const int* __restrict__ eids,
                       const int* __restrict__ offs, const float* __restrict__ npj,
                       const float* __restrict__ T, const float* __restrict__ bk,
                       const float* __restrict__ gk, const float* __restrict__ betak,
                       float* __restrict__ kf) {
    extern __shared__ float sh[];          // [Kp*OUTD] T tile + [OUTD] accumulator
    float* Tsh = sh;
    float* kfs = sh + Kp * OUTD;
    int d = blockIdx.x;
    int tid = threadIdx.x;                 // 256
    const float* Tg = T + (size_t)d * (Kp * OUTD);
    for (int i = tid; i < Kp * OUTD; i += 256) Tsh[i] = Tg[i];
    kfs[tid] = 0.f;
    __syncthreads();
    int e0 = offs[d], e1 = offs[d + 1];
    int lane = tid & 31, w = tid >> 5;     // 8 warps
    for (int i = e0 + w; i < e1; i += 8) {
        int e = eids[i];
        int s = src[e];
        float pv = (lane < Kp) ? npj[(size_t)s * Kp + lane] : 0.f;
        float p[Kp];
        #pragma unroll
        for (int a = 0; a < Kp; a++) p[a] = __shfl_sync(0xffffffffu, pv, a);
        float y[8];
        #pragma unroll
        for (int j = 0; j < 8; j++) {
            int o = j * 32 + lane;
            float acc = bk[o];
            #pragma unroll
            for (int a = 0; a < Kp; a++) acc += p[a] * Tsh[a * OUTD + o];
            y[j] = acc;
        }
        float sA = 0.f, sB = 0.f;
        #pragma unroll
        for (int j = 0; j < 8; j++) { sA += y[j]; sB += y[j] * y[j]; }
        sA = warp_sum(sA); sB = warp_sum(sB);
        float mu = sA * (1.f / 256.f);
        float var = sB * (1.f / 256.f) - mu * mu;
        float rs = rsqrtf(var + 1e-5f);
        #pragma unroll
        for (int j = 0; j < 8; j++) {
            int o = j * 32 + lane;
            float v = fmaxf((y[j] - mu) * rs * gk[o] + betak[o], 0.f);
            atomicAdd(&kfs[o], v);
        }
    }
    __syncthreads();
    kf[(size_t)d * OUTD + tid] = kfs[tid];
}

// ---------------- edge softmax + weighted src aggregation (warp per node) ----------------
__global__ void k_attn_ctx(const int* __restrict__ src, const int* __restrict__ eids,
                           const int* __restrict__ offs, const float* __restrict__ ad,
                           const float* __restrict__ as_, const float* __restrict__ be,
                           const float* __restrict__ hv, float* __restrict__ att,
                           float* __restrict__ ctx, int V) {
    int node = (blockIdx.x * blockDim.x + threadIdx.x) >> 5;
    int lane = threadIdx.x & 31;
    if (node >= V) return;
    int e0 = offs[node], e1 = offs[node + 1];
    float b = be[0];
    float advv = ad[node];
    // pass 1: logits + max
    float mx = -1e30f;
    for (int i = e0 + lane; i < e1; i += 32) {
        int e = eids[i];
        float lg = fmaxf(advv + as_[src[e]] + b, 0.f);
        att[i] = lg;
        mx = fmaxf(mx, lg);
    }
    mx = warp_max(mx);
    // pass 2: exp + sum
    float sm = 0.f;
    for (int i = e0 + lane; i < e1; i += 32) {
        float ex = expf(att[i] - mx);
        att[i] = ex;
        sm += ex;
    }
    sm = warp_sum(sm);
    float inv = (sm > 0.f) ? 1.f / sm : 0.f;
    // pass 3: context (whole warp per edge)
    float c[8];
    #pragma unroll
    for (int j = 0; j < 8; j++) c[j] = 0.f;
    for (int i = e0; i < e1; i++) {
        int e = eids[i];
        float wgt = att[i] * inv;
        const float* h = hv + (size_t)src[e] * Dg;
        #pragma unroll
        for (int j = 0; j < 8; j++) c[j] += wgt * h[j * 32 + lane];
    }
    float* cp = ctx + (size_t)node * Dg;
    #pragma unroll
    for (int j = 0; j < 8; j++) cp[j * 32 + lane] = fmaxf(c[j], 0.f);
}

// ---------------- tiled SGEMM: C[M,N] = A[M,K]*op(B) + bias ----------------
// TRANSB=false: B is [K,N] row-major. TRANSB=true: B is [N,K] row-major (C = A*B^T).
// Requires: N % 128 == 0, K % 8 == 0 (and %4 for float4), A/B 16B aligned.
template <bool TRANSB>
__global__ void sgemm(const float* __restrict__ A, const float* __restrict__ B,
                      const float* __restrict__ bias, float* __restrict__ C,
                      int M, int N, int Kd) {
    const int BM = 128, BN = 128, BK = 8;
    __shared__ float As[BK][BM];
    __shared__ float Bs[BK][BN + 4];
    int tid = threadIdx.x;                 // 256
    int bm = blockIdx.y * BM;
    int bn = blockIdx.x * BN;
    int arow = tid >> 1;
    int ak4 = (tid & 1) * 4;
    int ty = tid >> 4;                     // 0..15 -> rows
    int tx = tid & 15;                     // 0..15 -> cols
    float acc[8][8];
    #pragma unroll
    for (int i = 0; i < 8; i++)
        #pragma unroll
        for (int j = 0; j < 8; j++) acc[i][j] = 0.f;

    for (int k0 = 0; k0 < Kd; k0 += BK) {
        float4 av = make_float4(0.f, 0.f, 0.f, 0.f);
        int grow = bm + arow;
        if (grow < M) av = *(const float4*)(A + (size_t)grow * Kd + k0 + ak4);
        As[ak4 + 0][arow] = av.x;
        As[ak4 + 1][arow] = av.y;
        As[ak4 + 2][arow] = av.z;
        As[ak4 + 3][arow] = av.w;
        if (!TRANSB) {
            int bk = tid >> 5;
            int bnn = (tid & 31) * 4;
            float4 bv = *(const float4*)(B + (size_t)(k0 + bk) * N + bn + bnn);
            Bs[bk][bnn + 0] = bv.x; Bs[bk][bnn + 1] = bv.y;
            Bs[bk][bnn + 2] = bv.z; Bs[bk][bnn + 3] = bv.w;
        } else {
            int bnn = tid >> 1;
            int bk4 = (tid & 1) * 4;
            float4 bv = *(const float4*)(B + (size_t)(bn + bnn) * Kd + k0 + bk4);
            Bs[bk4 + 0][bnn] = bv.x; Bs[bk4 + 1][bnn] = bv.y;
            Bs[bk4 + 2][bnn] = bv.z; Bs[bk4 + 3][bnn] = bv.w;
        }
        __syncthreads();
        #pragma unroll
        for (int k = 0; k < BK; k++) {
            float a[8], bb[8];
            #pragma unroll
            for (int i = 0; i < 8; i++) a[i] = As[k][ty * 8 + i];
            #pragma unroll
            for (int j = 0; j < 8; j++) bb[j] = Bs[k][tx * 8 + j];
            #pragma unroll
            for (int i = 0; i < 8; i++)
                #pragma unroll
                for (int j = 0; j < 8; j++) acc[i][j] += a[i] * bb[j];
        }
        __syncthreads();
    }
    #pragma unroll
    for (int i = 0; i < 8; i++) {
        int r = bm + ty * 8 + i;
        if (r >= M) continue;
        #pragma unroll
        for (int j = 0; j < 8; j++) {
            int cidx = bn + tx * 8 + j;
            float v = acc[i][j] + (bias ? bias[cidx] : 0.f);
            C[(size_t)r * N + cidx] = v;
        }
    }
}

// ---------------- GRU elementwise + relu + LN + build cat ----------------
__global__ void k_gru(const float* __restrict__ gi, const float* __restrict__ gh,
                      const float* __restrict__ nf, const float* __restrict__ g_ln,
                      const float* __restrict__ b_ln, const float* __restrict__ kfeat,
                      float* __restrict__ cat_) {
    int v = blockIdx.x;
    int o = threadIdx.x;  // 256
    size_t b3 = (size_t)v * (3 * Dg);
    float ir = gi[b3 + o], iz = gi[b3 + Dg + o], inn = gi[b3 + 2 * Dg + o];
    float hr = gh[b3 + o], hz = gh[b3 + Dg + o], hn = gh[b3 + 2 * Dg + o];
    float x = nf[(size_t)v * Dg + o];
    float r = 1.f / (1.f + expf(-(ir + hr)));
    float z = 1.f / (1.f + expf(-(iz + hz)));
    float n = tanhf(inn + r * hn);
    float h = (1.f - z) * n + z * x;
    h = fmaxf(h, 0.f);
    float mu, rs;
    ln_stats_256(h, &mu, &rs);
    float g = (h - mu) * rs * g_ln[o] + b_ln[o];
    cat_[(size_t)v * (Dg + OUTD) + o] = g;
    cat_[(size_t)v * (Dg + OUTD) + Dg + o] = kfeat[(size_t)v * OUTD + o];
}

// ---------------- final LN + relu (in place on d_out) ----------------
__global__ void k_outln(float* __restrict__ out, const float* __restrict__ gc,
                        const float* __restrict__ betac) {
    int v = blockIdx.x;
    int o = threadIdx.x;
    float y = out[(size_t)v * Dg + o];
    float mu, rs;
    ln_stats_256(y, &mu, &rs);
    out[(size_t)v * Dg + o] = fmaxf((y - mu) * rs * gc[o] + betac[o], 0.f);
}

// ---------------- launch ----------------
extern "C" void kernel_launch(void* const* d_in, const int* in_sizes, int n_in,
                              void* d_out, int out_size) {
    const float* nf    = (const float*)d_in[0];
    const int*   src   = (const int*)d_in[1];
    const int*   dst   = (const int*)d_in[2];
    const float* Wp    = (const float*)d_in[3];
    const float* bp    = (const float*)d_in[4];
    const float* gp    = (const float*)d_in[5];
    const float* betap = (const float*)d_in[6];
    const float* Wk    = (const float*)d_in[7];
    const float* bk    = (const float*)d_in[8];
    const float* gk    = (const float*)d_in[9];
    const float* betak = (const float*)d_in[10];
    const float* We    = (const float*)d_in[11];
    const float* be    = (const float*)d_in[12];
    const float* Wn    = (const float*)d_in[13];
    const float* bn    = (const float*)d_in[14];
    const float* W_ih  = (const float*)d_in[15];
    const float* W_hh  = (const float*)d_in[16];
    const float* b_ih  = (const float*)d_in[17];
    const float* b_hh  = (const float*)d_in[18];
    const float* g_ln  = (const float*)d_in[19];
    const float* b_ln  = (const float*)d_in[20];
    const float* Wc    = (const float*)d_in[21];
    const float* bc    = (const float*)d_in[22];
    const float* gc    = (const float*)d_in[23];
    const float* betac = (const float*)d_in[24];

    int V = in_sizes[0] / Dg;
    int E = in_sizes[1];
    float* out = (float*)d_out;

    // scratch symbol addresses (device globals)
    float *npj, *ad, *as_, *hv, *T, *att, *ctx, *kf, *gi, *gh, *cat_;
    int *deg, *offs, *cursor, *eids;
    cudaGetSymbolAddress((void**)&npj, g_npj);
    cudaGetSymbolAddress((void**)&ad, g_ad);
    cudaGetSymbolAddress((void**)&as_, g_as);
    cudaGetSymbolAddress((void**)&hv, g_hv);
    cudaGetSymbolAddress((void**)&T, g_T);
    cudaGetSymbolAddress((void**)&att, g_att);
    cudaGetSymbolAddress((void**)&ctx, g_ctx);
    cudaGetSymbolAddress((void**)&kf, g_kf);
    cudaGetSymbolAddress((void**)&gi, g_gi);
    cudaGetSymbolAddress((void**)&gh, g_gh);
    cudaGetSymbolAddress((void**)&cat_, g_cat);
    cudaGetSymbolAddress((void**)&deg, g_deg);
    cudaGetSymbolAddress((void**)&offs, g_offs);
    cudaGetSymbolAddress((void**)&cursor, g_cursor);
    cudaGetSymbolAddress((void**)&eids, g_eids);

    // --- CSR build over dst ---
    k_zero_int<<<256, 256>>>(deg, V);
    k_hist<<<592, 256>>>(dst, deg, E);
    k_scan<<<1, 1024>>>(deg, offs, V);
    k_copy_int<<<256, 256>>>(offs, cursor, V);
    k_scatter<<<592, 256>>>(dst, cursor, eids, E);

    // --- node projections ---
    k_npj<<<(V + 7) / 8, 256>>>(nf, Wp, bp, gp, betap, We, npj, ad, as_, V);

    // hv = nf @ Wn + bn
    {
        dim3 grid(Dg / 128, (V + 127) / 128);
        sgemm<false><<<grid, 256>>>(nf, Wn, bn, hv, V, Dg, Dg);
    }

    // T = npj x Wk (per-node 20x256 factor matrices)
    k_T<<<(V + 15) / 16, 256>>>(npj, Wk, T, V);

    // edge softmax + weighted aggregation
    k_attn_ctx<<<(V + 7) / 8, 256>>>(src, eids, offs, ad, as_, be, hv, att, ctx, V);

    // kron branch per-node
    k_kron<<<V, 256, (Kp * OUTD + OUTD) * sizeof(float)>>>(src, eids, offs, npj, T, bk, gk, betak, kf);

    // GRU input gemms: gi = ctx @ W_ih^T, gh = nf @ W_hh^T
    {
        dim3 grid(3 * Dg / 128, (V + 127) / 128);
        sgemm<true><<<grid, 256>>>(ctx, W_ih, b_ih, gi, V, 3 * Dg, Dg);
        sgemm<true><<<grid, 256>>>(nf, W_hh, b_hh, gh, V, 3 * Dg, Dg);
    }

    // GRU elementwise + LN + cat build
    k_gru<<<V, 256>>>(gi, gh, nf, g_ln, b_ln, kf, cat_);

    // final: out = cat @ Wc + bc, then LN + relu
    {
        dim3 grid(Dg / 128, (V + 127) / 128);
        sgemm<false><<<grid, 256>>>(cat_, Wc, bc, out, V, Dg, Dg + OUTD);
    }
    k_outln<<<V, 256>>>(out, gc, betac);
}